// round 1
// baseline (speedup 1.0000x reference)
#include <cuda_runtime.h>
#include <math.h>

// Problem constants (fixed by setup_inputs)
#define B_   64
#define L_   680
#define C_   1024
#define NSEG 10

// Segment geometry: lens = p^2 for PATCH_NUMS, starts = cumsum
static const int       h_start[NSEG] = {0,1,5,14,30,55,91,155,255,424};
static const int       h_len[NSEG]   = {1,4,9,16,25,36,64,100,169,256};
// base offsets (floats) of each segment's score block: 64 * cumsum(len_i * 128*(i+1))
static const long long h_base[NSEG]  = {0LL,8192LL,73728LL,294912LL,819200LL,
                                        1843200LL,3612672LL,7282688LL,13836288LL,26296320LL};

__constant__ int       c_start[NSEG] = {0,1,5,14,30,55,91,155,255,424};
__constant__ int       c_len[NSEG]   = {1,4,9,16,25,36,64,100,169,256};
__constant__ long long c_base[NSEG]  = {0LL,8192LL,73728LL,294912LL,819200LL,
                                        1843200LL,3612672LL,7282688LL,13836288LL,26296320LL};

// Static device scratch (allocation-free rule: __device__ globals)
__device__ float g_Q  [44564480];   // 43520 x 1024
__device__ float g_K  [1310720];    // 1280 x 1024
__device__ float g_V  [1310720];    // 1280 x 1024
__device__ float g_S  [47267840];   // all score/attn blocks
__device__ float g_MC [44564480];   // mem_combined, 43520 x 1024
__device__ float g_mid[2785280];    // 43520 x 64

// ---------------------------------------------------------------------------
// Tiled SGEMM: C = A @ op(B) (+bias) (*sigmoid(gate))
// A: [M,K] row-major (lda), B: [K,N] (NN) or [N,K] (NT, ldb = K-stride)
// Batched via blockIdx.z with element strides bsA/bsB/bsC.
// BM=BN=128, BK=8, 256 threads, 8x8 per-thread microtile.
// Requires K % 8 == 0 (true for all uses: 1024, 64, 128*(i+1)).
// M and N edges fully guarded.
// ---------------------------------------------------------------------------
template<int TRANSB>
__global__ __launch_bounds__(256)
void gemm_kernel(const float* __restrict__ A, int lda, long long bsA,
                 const float* __restrict__ Bm, int ldb, long long bsB,
                 float* __restrict__ Cc, int ldc, long long bsC,
                 int M, int N, int K,
                 const float* __restrict__ bias,
                 const float* __restrict__ gate_logit)
{
    __shared__ float As[8][128];
    __shared__ float Bs[8][128 + 4];

    const int z = blockIdx.z;
    A  += (long long)z * bsA;
    Bm += (long long)z * bsB;
    Cc += (long long)z * bsC;

    const int m0 = blockIdx.y * 128;
    const int n0 = blockIdx.x * 128;
    const int tid = threadIdx.x;
    const int tx = tid & 15;     // N direction (x8)
    const int ty = tid >> 4;     // M direction (x8)

    float acc[8][8];
    #pragma unroll
    for (int i = 0; i < 8; i++)
        #pragma unroll
        for (int j = 0; j < 8; j++) acc[i][j] = 0.f;

    float ar[8], br[8];

    for (int k0 = 0; k0 < K; k0 += 8) {
        // --- load A tile 128x8 (transposed into As[k][m]) ---
        {
            int r = tid >> 1;
            int c = (tid & 1) * 4;
            float4 v = make_float4(0.f, 0.f, 0.f, 0.f);
            if (m0 + r < M)
                v = *(const float4*)&A[(long long)(m0 + r) * lda + k0 + c];
            As[c + 0][r] = v.x; As[c + 1][r] = v.y;
            As[c + 2][r] = v.z; As[c + 3][r] = v.w;
        }
        // --- load B tile ---
        if (!TRANSB) {
            // B[K,N]: 8 rows x 128 cols
            int r = tid >> 5;
            int c = (tid & 31) * 4;
            float4 v = make_float4(0.f, 0.f, 0.f, 0.f);
            if (n0 + c < N)
                v = *(const float4*)&Bm[(long long)(k0 + r) * ldb + n0 + c];
            Bs[r][c + 0] = v.x; Bs[r][c + 1] = v.y;
            Bs[r][c + 2] = v.z; Bs[r][c + 3] = v.w;
        } else {
            // B[N,K]: need Bs[k][n] = B[n0+n, k0+k]
            int n = tid >> 1;
            int kk = (tid & 1) * 4;
            float4 v = make_float4(0.f, 0.f, 0.f, 0.f);
            if (n0 + n < N)
                v = *(const float4*)&Bm[(long long)(n0 + n) * ldb + k0 + kk];
            Bs[kk + 0][n] = v.x; Bs[kk + 1][n] = v.y;
            Bs[kk + 2][n] = v.z; Bs[kk + 3][n] = v.w;
        }
        __syncthreads();

        #pragma unroll
        for (int k = 0; k < 8; k++) {
            #pragma unroll
            for (int i = 0; i < 8; i++) ar[i] = As[k][ty * 8 + i];
            #pragma unroll
            for (int j = 0; j < 8; j++) br[j] = Bs[k][tx * 8 + j];
            #pragma unroll
            for (int i = 0; i < 8; i++)
                #pragma unroll
                for (int j = 0; j < 8; j++)
                    acc[i][j] += ar[i] * br[j];
        }
        __syncthreads();
    }

    float gate = 1.0f;
    if (gate_logit) gate = 1.0f / (1.0f + expf(-(*gate_logit)));

    #pragma unroll
    for (int i = 0; i < 8; i++) {
        int m = m0 + ty * 8 + i;
        if (m >= M) continue;
        #pragma unroll
        for (int j = 0; j < 8; j++) {
            int n = n0 + tx * 8 + j;
            if (n >= N) continue;
            float v = acc[i][j];
            if (bias) v += bias[n];
            v *= gate;
            Cc[(long long)m * ldc + n] = v;
        }
    }
}

// ---------------------------------------------------------------------------
// Row softmax over the segment-packed score buffer g_S.
// One block (256 threads) per (b, l) row. Applies scale = (1/32)/clip(exp(lt)).
// ---------------------------------------------------------------------------
__global__ void softmax_kernel(const float* __restrict__ log_temp)
{
    int row = blockIdx.x;           // b*L + l
    int b = row / L_;
    int l = row - b * L_;

    int seg = 0;
    #pragma unroll
    for (int s2 = 1; s2 < NSEG; s2++)
        if (l >= c_start[s2]) seg = s2;

    const int n   = 128 * (seg + 1);
    const int len = c_len[seg];
    float* p = g_S + c_base[seg] + ((long long)b * len + (l - c_start[seg])) * (long long)n;

    float t = expf(*log_temp);
    t = fminf(fmaxf(t, 0.05f), 1.0f);
    const float scale = (1.0f / 32.0f) / t;   // inv_scale = 1/sqrt(1024)

    __shared__ float sh[8];
    const int lane = threadIdx.x & 31;
    const int w    = threadIdx.x >> 5;

    // max
    float m = -1e30f;
    for (int j = threadIdx.x; j < n; j += 256) m = fmaxf(m, p[j] * scale);
    #pragma unroll
    for (int o = 16; o; o >>= 1) m = fmaxf(m, __shfl_xor_sync(0xffffffffu, m, o));
    if (lane == 0) sh[w] = m;
    __syncthreads();
    m = sh[lane & 7];
    #pragma unroll
    for (int o = 4; o; o >>= 1) m = fmaxf(m, __shfl_xor_sync(0xffffffffu, m, o));

    // exp + sum (store exp in-place)
    float sum = 0.f;
    for (int j = threadIdx.x; j < n; j += 256) {
        float e = expf(p[j] * scale - m);
        p[j] = e;
        sum += e;
    }
    #pragma unroll
    for (int o = 16; o; o >>= 1) sum += __shfl_xor_sync(0xffffffffu, sum, o);
    __syncthreads();
    if (lane == 0) sh[w] = sum;
    __syncthreads();
    sum = sh[lane & 7];
    #pragma unroll
    for (int o = 4; o; o >>= 1) sum += __shfl_xor_sync(0xffffffffu, sum, o);

    const float inv = 1.0f / sum;
    for (int j = threadIdx.x; j < n; j += 256) p[j] *= inv;
}

__global__ void tail_kernel(float* out, long long off)
{
    if (threadIdx.x < 2) out[off + threadIdx.x] = 0.f;
}

// ---------------------------------------------------------------------------
// Host-side launch helper
// ---------------------------------------------------------------------------
static void launch_gemm(bool transB,
                        const float* A, int lda, long long bsA,
                        const float* Bm, int ldb, long long bsB,
                        float* Cc, int ldc, long long bsC,
                        int M, int N, int K,
                        const float* bias, const float* gate, int Z)
{
    dim3 grid((N + 127) / 128, (M + 127) / 128, Z);
    if (transB)
        gemm_kernel<1><<<grid, 256>>>(A, lda, bsA, Bm, ldb, bsB, Cc, ldc, bsC,
                                      M, N, K, bias, gate);
    else
        gemm_kernel<0><<<grid, 256>>>(A, lda, bsA, Bm, ldb, bsB, Cc, ldc, bsC,
                                      M, N, K, bias, gate);
}

extern "C" void kernel_launch(void* const* d_in, const int* in_sizes, int n_in,
                              void* d_out, int out_size)
{
    const float* x   = (const float*)d_in[0];
    const float* mem = (const float*)d_in[1];
    const float* Wq  = (const float*)d_in[2];
    const float* Wk  = (const float*)d_in[3];
    const float* Wv  = (const float*)d_in[4];
    const float* wk1 = (const float*)d_in[5];
    const float* bk1 = (const float*)d_in[6];
    const float* wk2 = (const float*)d_in[7];
    const float* bk2 = (const float*)d_in[8];
    const float* wv1 = (const float*)d_in[9];
    const float* bv1 = (const float*)d_in[10];
    const float* wv2 = (const float*)d_in[11];
    const float* bv2 = (const float*)d_in[12];
    const float* gk  = (const float*)d_in[13];
    const float* gv  = (const float*)d_in[14];
    const float* lt  = (const float*)d_in[15];
    float* out = (float*)d_out;

    float *Q, *Kp, *Vp, *S, *MC, *mid;
    cudaGetSymbolAddress((void**)&Q,   g_Q);
    cudaGetSymbolAddress((void**)&Kp,  g_K);
    cudaGetSymbolAddress((void**)&Vp,  g_V);
    cudaGetSymbolAddress((void**)&S,   g_S);
    cudaGetSymbolAddress((void**)&MC,  g_MC);
    cudaGetSymbolAddress((void**)&mid, g_mid);

    // 1) projections
    launch_gemm(false, x,   C_, 0, Wq, C_, 0, Q,  C_, 0, B_ * L_,    C_, C_, nullptr, nullptr, 1);
    launch_gemm(false, mem, C_, 0, Wk, C_, 0, Kp, C_, 0, NSEG * 128, C_, C_, nullptr, nullptr, 1);
    launch_gemm(false, mem, C_, 0, Wv, C_, 0, Vp, C_, 0, NSEG * 128, C_, C_, nullptr, nullptr, 1);

    // 2) scores per segment: S_i[b,l,n] = Q[b, s_i+l, :] . K[n, :]   (NT)
    for (int i = 0; i < NSEG; i++) {
        int n = 128 * (i + 1), len = h_len[i], s = h_start[i];
        launch_gemm(true,
                    Q + (long long)s * C_, C_, (long long)L_ * C_,
                    Kp, C_, 0,
                    S + h_base[i], n, (long long)len * n,
                    len, n, C_, nullptr, nullptr, B_);
    }

    // 3) softmax (in-place on g_S), includes 1/(32*temp) scale
    softmax_kernel<<<B_ * L_, 256>>>(lt);

    // 4) mem_combined per segment: MC[b, s_i+l, :] = attn_i @ V[:n_i]  (NN)
    for (int i = 0; i < NSEG; i++) {
        int n = 128 * (i + 1), len = h_len[i], s = h_start[i];
        launch_gemm(false,
                    S + h_base[i], n, (long long)len * n,
                    Vp, C_, 0,
                    MC + (long long)s * C_, C_, (long long)L_ * C_,
                    len, C_, n, nullptr, nullptr, B_);
    }

    // 5) bottleneck k: mid = MC@wk1 + bk1 ; mem_k = sigmoid(gk)*(mid@wk2 + bk2)
    launch_gemm(false, MC,  C_, 0, wk1, 64, 0, mid, 64, 0, B_ * L_, 64, C_, bk1, nullptr, 1);
    launch_gemm(false, mid, 64, 0, wk2, C_, 0, out, C_, 0, B_ * L_, C_, 64, bk2, gk,      1);

    // 6) bottleneck v
    launch_gemm(false, MC,  C_, 0, wv1, 64, 0, mid, 64, 0, B_ * L_, 64, C_, bv1, nullptr, 1);
    launch_gemm(false, mid, 64, 0, wv2, C_, 0, out + (long long)B_ * L_ * C_, C_, 0,
                B_ * L_, C_, 64, bv2, gv, 1);

    // 7) trailing two scalar zeros
    tail_kernel<<<1, 32>>>(out, 2LL * B_ * L_ * C_);
}

// round 2
// speedup vs baseline: 1.5082x; 1.5082x over previous
#include <cuda_runtime.h>
#include <math.h>
#include <stdint.h>

// Problem constants (fixed by setup_inputs)
#define B_   64
#define L_   680
#define C_   1024
#define NSEG 10

static const int       h_start[NSEG] = {0,1,5,14,30,55,91,155,255,424};
static const int       h_len[NSEG]   = {1,4,9,16,25,36,64,100,169,256};
static const long long h_base[NSEG]  = {0LL,8192LL,73728LL,294912LL,819200LL,
                                        1843200LL,3612672LL,7282688LL,13836288LL,26296320LL};

__constant__ int       c_start[NSEG] = {0,1,5,14,30,55,91,155,255,424};
__constant__ int       c_len[NSEG]   = {1,4,9,16,25,36,64,100,169,256};
__constant__ long long c_base[NSEG]  = {0LL,8192LL,73728LL,294912LL,819200LL,
                                        1843200LL,3612672LL,7282688LL,13836288LL,26296320LL};

// Static device scratch
__device__ float g_Q  [44564480];   // 43520 x 1024
__device__ float g_K  [1310720];    // 1280 x 1024
__device__ float g_V  [1310720];    // 1280 x 1024
__device__ float g_S  [47267840];   // segment-packed scores/attn
__device__ float g_MC [44564480];   // mem_combined, 43520 x 1024
__device__ float g_mid[2785280];    // 43520 x 64

__device__ __forceinline__ float f2tf32(float x) {
    uint32_t r;
    asm("cvt.rna.tf32.f32 %0, %1;" : "=r"(r) : "f"(x));
    float out;
    asm("mov.b32 %0, %1;" : "=f"(out) : "r"(r));
    return out;
}

// ---------------------------------------------------------------------------
// TF32 tensor-core GEMM: C = A @ op(B) (+bias) (*sigmoid(gate))
//   A: [M,K] row-major (lda); rows optionally remapped:
//       alen>0  =>  global row = (m/alen)*680 + astart + (m%alen)
//   B: NN = [K,N] (ldb), NT = [N,K] (ldb)
//   C: [M,N] (ldc); rows optionally remapped with clen/cstart (same formula)
// Requirements (all satisfied by this problem): M%64==0, N%64==0, K%16==0,
// 16-byte aligned rows (all lda/ldb multiples of 4? here 64/128*i/1024 -> yes).
// Block: 128 threads, BM=BN=64, BK=16. Warp w owns 32x32 at
// (wm=(w&1)*32, wn=(w>>1)*32) computed as 2x4 grid of m16n8k8 mma.
// ---------------------------------------------------------------------------
template<int TRANSB>
__global__ __launch_bounds__(128)
void tgemm(const float* __restrict__ A, int lda,
           const float* __restrict__ B, int ldb,
           float* __restrict__ C, int ldc,
           int M, int N, int K,
           int alen, int astart, int clen, int cstart,
           const float* __restrict__ bias,
           const float* __restrict__ gate_logit)
{
    __shared__ float As[16][65];
    __shared__ float Bs[16][65];

    const int tid  = threadIdx.x;
    const int m0   = blockIdx.y * 64;
    const int n0   = blockIdx.x * 64;
    const int lane = tid & 31;
    const int w    = tid >> 5;
    const int wm   = (w & 1) * 32;
    const int wn   = (w >> 1) * 32;
    const int g    = lane >> 2;     // group id 0..7
    const int t4   = lane & 3;      // thread-in-group 0..3

    float acc[2][4][4];
    #pragma unroll
    for (int i = 0; i < 2; i++)
        #pragma unroll
        for (int j = 0; j < 4; j++)
            #pragma unroll
            for (int k = 0; k < 4; k++) acc[i][j][k] = 0.f;

    // A load pointer: thread loads row m0+(tid>>1), cols (tid&1)*8 .. +7
    {
    }
    const int am = m0 + (tid >> 1);
    long long arow = (alen > 0)
        ? (long long)(am / alen) * L_ + astart + (am % alen)
        : (long long)am;
    const float* Aptr = A + arow * (long long)lda + (tid & 1) * 8;
    const int a_sm = tid >> 1;
    const int a_sk = (tid & 1) * 8;

    const float* Bptr;
    if (!TRANSB) Bptr = B + (long long)(tid >> 3) * ldb + n0 + (tid & 7) * 8;
    else         Bptr = B + (long long)(n0 + (tid >> 1)) * ldb + (tid & 1) * 8;

    for (int k0 = 0; k0 < K; k0 += 16) {
        // ---- A tile 64x16, stored transposed As[k][m] (tf32-converted) ----
        {
            float4 v0 = *(const float4*)(Aptr + k0);
            float4 v1 = *(const float4*)(Aptr + k0 + 4);
            As[a_sk + 0][a_sm] = f2tf32(v0.x);
            As[a_sk + 1][a_sm] = f2tf32(v0.y);
            As[a_sk + 2][a_sm] = f2tf32(v0.z);
            As[a_sk + 3][a_sm] = f2tf32(v0.w);
            As[a_sk + 4][a_sm] = f2tf32(v1.x);
            As[a_sk + 5][a_sm] = f2tf32(v1.y);
            As[a_sk + 6][a_sm] = f2tf32(v1.z);
            As[a_sk + 7][a_sm] = f2tf32(v1.w);
        }
        // ---- B tile -> Bs[k][n] ----
        if (!TRANSB) {
            const float* p = Bptr + (long long)k0 * ldb;
            float4 v0 = *(const float4*)(p);
            float4 v1 = *(const float4*)(p + 4);
            int bk = tid >> 3, bn = (tid & 7) * 8;
            Bs[bk][bn + 0] = f2tf32(v0.x);
            Bs[bk][bn + 1] = f2tf32(v0.y);
            Bs[bk][bn + 2] = f2tf32(v0.z);
            Bs[bk][bn + 3] = f2tf32(v0.w);
            Bs[bk][bn + 4] = f2tf32(v1.x);
            Bs[bk][bn + 5] = f2tf32(v1.y);
            Bs[bk][bn + 6] = f2tf32(v1.z);
            Bs[bk][bn + 7] = f2tf32(v1.w);
        } else {
            float4 v0 = *(const float4*)(Bptr + k0);
            float4 v1 = *(const float4*)(Bptr + k0 + 4);
            int bn = tid >> 1, bk = (tid & 1) * 8;
            Bs[bk + 0][bn] = f2tf32(v0.x);
            Bs[bk + 1][bn] = f2tf32(v0.y);
            Bs[bk + 2][bn] = f2tf32(v0.z);
            Bs[bk + 3][bn] = f2tf32(v0.w);
            Bs[bk + 4][bn] = f2tf32(v1.x);
            Bs[bk + 5][bn] = f2tf32(v1.y);
            Bs[bk + 6][bn] = f2tf32(v1.z);
            Bs[bk + 7][bn] = f2tf32(v1.w);
        }
        __syncthreads();

        #pragma unroll
        for (int kb = 0; kb < 16; kb += 8) {
            uint32_t af[2][4], bf[4][2];
            #pragma unroll
            for (int mi = 0; mi < 2; mi++) {
                int mb = wm + mi * 16;
                af[mi][0] = __float_as_uint(As[kb + t4    ][mb + g    ]);
                af[mi][1] = __float_as_uint(As[kb + t4    ][mb + g + 8]);
                af[mi][2] = __float_as_uint(As[kb + t4 + 4][mb + g    ]);
                af[mi][3] = __float_as_uint(As[kb + t4 + 4][mb + g + 8]);
            }
            #pragma unroll
            for (int ni = 0; ni < 4; ni++) {
                int nb = wn + ni * 8;
                bf[ni][0] = __float_as_uint(Bs[kb + t4    ][nb + g]);
                bf[ni][1] = __float_as_uint(Bs[kb + t4 + 4][nb + g]);
            }
            #pragma unroll
            for (int mi = 0; mi < 2; mi++)
                #pragma unroll
                for (int ni = 0; ni < 4; ni++) {
                    asm volatile(
                        "mma.sync.aligned.m16n8k8.row.col.f32.tf32.tf32.f32 "
                        "{%0,%1,%2,%3},{%4,%5,%6,%7},{%8,%9},{%0,%1,%2,%3};"
                        : "+f"(acc[mi][ni][0]), "+f"(acc[mi][ni][1]),
                          "+f"(acc[mi][ni][2]), "+f"(acc[mi][ni][3])
                        : "r"(af[mi][0]), "r"(af[mi][1]),
                          "r"(af[mi][2]), "r"(af[mi][3]),
                          "r"(bf[ni][0]), "r"(bf[ni][1]));
                }
        }
        __syncthreads();
    }

    float gate = 1.0f;
    if (gate_logit) gate = 1.0f / (1.0f + expf(-(*gate_logit)));

    #pragma unroll
    for (int mi = 0; mi < 2; mi++) {
        #pragma unroll
        for (int rr = 0; rr < 2; rr++) {
            int m = m0 + wm + mi * 16 + g + rr * 8;
            long long crow = (clen > 0)
                ? (long long)(m / clen) * L_ + cstart + (m % clen)
                : (long long)m;
            float* cp = C + crow * (long long)ldc;
            #pragma unroll
            for (int ni = 0; ni < 4; ni++) {
                int n = n0 + wn + ni * 8 + t4 * 2;
                float v0 = acc[mi][ni][rr * 2 + 0];
                float v1 = acc[mi][ni][rr * 2 + 1];
                if (bias) { v0 += bias[n]; v1 += bias[n + 1]; }
                cp[n]     = v0 * gate;
                cp[n + 1] = v1 * gate;
            }
        }
    }
}

// ---------------------------------------------------------------------------
// Row softmax over segment-packed g_S; scale = (1/32)/clip(exp(log_temp))
// ---------------------------------------------------------------------------
__global__ void softmax_kernel(const float* __restrict__ log_temp)
{
    int row = blockIdx.x;           // b*L + l
    int b = row / L_;
    int l = row - b * L_;

    int seg = 0;
    #pragma unroll
    for (int s2 = 1; s2 < NSEG; s2++)
        if (l >= c_start[s2]) seg = s2;

    const int n   = 128 * (seg + 1);
    const int len = c_len[seg];
    float* p = g_S + c_base[seg] + ((long long)b * len + (l - c_start[seg])) * (long long)n;

    float t = expf(*log_temp);
    t = fminf(fmaxf(t, 0.05f), 1.0f);
    const float scale = (1.0f / 32.0f) / t;

    __shared__ float sh[8];
    const int lane = threadIdx.x & 31;
    const int w    = threadIdx.x >> 5;

    float m = -1e30f;
    for (int j = threadIdx.x; j < n; j += 256) m = fmaxf(m, p[j] * scale);
    #pragma unroll
    for (int o = 16; o; o >>= 1) m = fmaxf(m, __shfl_xor_sync(0xffffffffu, m, o));
    if (lane == 0) sh[w] = m;
    __syncthreads();
    m = sh[lane & 7];
    #pragma unroll
    for (int o = 4; o; o >>= 1) m = fmaxf(m, __shfl_xor_sync(0xffffffffu, m, o));

    float sum = 0.f;
    for (int j = threadIdx.x; j < n; j += 256) {
        float e = expf(p[j] * scale - m);
        p[j] = e;
        sum += e;
    }
    #pragma unroll
    for (int o = 16; o; o >>= 1) sum += __shfl_xor_sync(0xffffffffu, sum, o);
    __syncthreads();
    if (lane == 0) sh[w] = sum;
    __syncthreads();
    sum = sh[lane & 7];
    #pragma unroll
    for (int o = 4; o; o >>= 1) sum += __shfl_xor_sync(0xffffffffu, sum, o);

    const float inv = 1.0f / sum;
    for (int j = threadIdx.x; j < n; j += 256) p[j] *= inv;
}

__global__ void tail_kernel(float* out, long long off)
{
    if (threadIdx.x < 2) out[off + threadIdx.x] = 0.f;
}

// ---------------------------------------------------------------------------
static void launch_tgemm(bool transB,
                         const float* A, int lda,
                         const float* B, int ldb,
                         float* C, int ldc,
                         int M, int N, int K,
                         int alen, int astart, int clen, int cstart,
                         const float* bias, const float* gate)
{
    dim3 grid(N / 64, M / 64);
    if (transB)
        tgemm<1><<<grid, 128>>>(A, lda, B, ldb, C, ldc, M, N, K,
                                alen, astart, clen, cstart, bias, gate);
    else
        tgemm<0><<<grid, 128>>>(A, lda, B, ldb, C, ldc, M, N, K,
                                alen, astart, clen, cstart, bias, gate);
}

extern "C" void kernel_launch(void* const* d_in, const int* in_sizes, int n_in,
                              void* d_out, int out_size)
{
    const float* x   = (const float*)d_in[0];
    const float* mem = (const float*)d_in[1];
    const float* Wq  = (const float*)d_in[2];
    const float* Wk  = (const float*)d_in[3];
    const float* Wv  = (const float*)d_in[4];
    const float* wk1 = (const float*)d_in[5];
    const float* bk1 = (const float*)d_in[6];
    const float* wk2 = (const float*)d_in[7];
    const float* bk2 = (const float*)d_in[8];
    const float* wv1 = (const float*)d_in[9];
    const float* bv1 = (const float*)d_in[10];
    const float* wv2 = (const float*)d_in[11];
    const float* bv2 = (const float*)d_in[12];
    const float* gk  = (const float*)d_in[13];
    const float* gv  = (const float*)d_in[14];
    const float* lt  = (const float*)d_in[15];
    float* out = (float*)d_out;

    float *Q, *Kp, *Vp, *S, *MC, *mid;
    cudaGetSymbolAddress((void**)&Q,   g_Q);
    cudaGetSymbolAddress((void**)&Kp,  g_K);
    cudaGetSymbolAddress((void**)&Vp,  g_V);
    cudaGetSymbolAddress((void**)&S,   g_S);
    cudaGetSymbolAddress((void**)&MC,  g_MC);
    cudaGetSymbolAddress((void**)&mid, g_mid);

    // 1) projections
    launch_tgemm(false, x,   C_, Wq, C_, Q,  C_, B_ * L_,    C_, C_, 0,0,0,0, nullptr, nullptr);
    launch_tgemm(false, mem, C_, Wk, C_, Kp, C_, NSEG * 128, C_, C_, 0,0,0,0, nullptr, nullptr);
    launch_tgemm(false, mem, C_, Wv, C_, Vp, C_, NSEG * 128, C_, C_, 0,0,0,0, nullptr, nullptr);

    // 2) scores per segment (flattened M = 64*len, A rows remapped into Q)
    for (int i = 0; i < NSEG; i++) {
        int n = 128 * (i + 1), len = h_len[i], s = h_start[i];
        launch_tgemm(true,
                     Q, C_,
                     Kp, C_,
                     S + h_base[i], n,
                     B_ * len, n, C_,
                     len, s, 0, 0, nullptr, nullptr);
    }

    // 3) softmax in-place
    softmax_kernel<<<B_ * L_, 256>>>(lt);

    // 4) attn @ V per segment (C rows remapped into MC)
    for (int i = 0; i < NSEG; i++) {
        int n = 128 * (i + 1), len = h_len[i], s = h_start[i];
        launch_tgemm(false,
                     S + h_base[i], n,
                     Vp, C_,
                     MC, C_,
                     B_ * len, C_, n,
                     0, 0, len, s, nullptr, nullptr);
    }

    // 5) bottleneck k
    launch_tgemm(false, MC,  C_, wk1, 64, mid, 64, B_ * L_, 64, C_, 0,0,0,0, bk1, nullptr);
    launch_tgemm(false, mid, 64, wk2, C_, out, C_, B_ * L_, C_, 64, 0,0,0,0, bk2, gk);

    // 6) bottleneck v
    launch_tgemm(false, MC,  C_, wv1, 64, mid, 64, B_ * L_, 64, C_, 0,0,0,0, bv1, nullptr);
    launch_tgemm(false, mid, 64, wv2, C_, out + (long long)B_ * L_ * C_, C_,
                 B_ * L_, C_, 64, 0,0,0,0, bv2, gv);

    // 7) trailing two scalar zeros
    tail_kernel<<<1, 32>>>(out, 2LL * B_ * L_ * C_);
}

// round 3
// speedup vs baseline: 3.2123x; 2.1298x over previous
#include <cuda_runtime.h>
#include <math.h>
#include <stdint.h>

// Problem constants (fixed by setup_inputs)
#define B_   64
#define L_   680
#define C_   1024
#define NSEG 10

static const int       h_start[NSEG] = {0,1,5,14,30,55,91,155,255,424};
static const int       h_len[NSEG]   = {1,4,9,16,25,36,64,100,169,256};
static const long long h_base[NSEG]  = {0LL,8192LL,73728LL,294912LL,819200LL,
                                        1843200LL,3612672LL,7282688LL,13836288LL,26296320LL};

__constant__ int       c_start[NSEG] = {0,1,5,14,30,55,91,155,255,424};
__constant__ int       c_len[NSEG]   = {1,4,9,16,25,36,64,100,169,256};
__constant__ long long c_base[NSEG]  = {0LL,8192LL,73728LL,294912LL,819200LL,
                                        1843200LL,3612672LL,7282688LL,13836288LL,26296320LL};

// Static device scratch
__device__ float g_Q  [44564480];   // 43520 x 1024
__device__ float g_K  [1310720];    // 1280 x 1024
__device__ float g_V  [1310720];    // 1280 x 1024
__device__ float g_S  [47267840];   // segment-packed scores/attn
__device__ float g_MC [44564480];   // mem_combined, 43520 x 1024
__device__ float g_mid[5570560];    // 43520 x 128 (mid_k | mid_v)
__device__ float g_w12[131072];     // 1024 x 128 (wk1 | wv1)
__device__ float g_b12[128];        // bk1 | bv1

__device__ __forceinline__ float f2tf32(float x) {
    uint32_t r;
    asm("cvt.rna.tf32.f32 %0, %1;" : "=r"(r) : "f"(x));
    float out;
    asm("mov.b32 %0, %1;" : "=f"(out) : "r"(r));
    return out;
}

// ---------------------------------------------------------------------------
// TF32 tensor-core GEMM, 128x128x16 tiles, 256 threads, double-buffered smem.
//   C = A @ op(B) (+bias) (*sigmoid(gate))
//   A: [M,K] row-major (lda); rows optionally remapped:
//       alen>0  =>  global row = (m/alen)*680 + astart + (m%alen)
//   B: NN = [K,N] (ldb), NT = [N,K] (ldb)
//   C: [M,N] (ldc); rows optionally remapped via clen/cstart
// K % 16 == 0 required. M, N edges guarded.
// 8 warps: warp (w) owns 64x32 at (wm=(w&1)*64, wn=(w>>1)*32):
//   4x4 grid of m16n8k8 tf32 mma fragments.
// Smem stride 136 (mod 32 = 8) -> all fragment LDS are conflict-free.
// ---------------------------------------------------------------------------
template<int TRANSB>
__global__ __launch_bounds__(256)
void tgemm(const float* __restrict__ A, int lda,
           const float* __restrict__ B, int ldb,
           float* __restrict__ C, int ldc,
           int M, int N, int K,
           int alen, int astart, int clen, int cstart,
           const float* __restrict__ bias,
           const float* __restrict__ gate_logit)
{
    __shared__ float As[2][16][136];
    __shared__ float Bs[2][16][136];

    const int tid  = threadIdx.x;
    const int m0   = blockIdx.y * 128;
    const int n0   = blockIdx.x * 128;
    const int lane = tid & 31;
    const int w    = tid >> 5;
    const int wm   = (w & 1) * 64;
    const int wn   = (w >> 1) * 32;
    const int g    = lane >> 2;     // 0..7
    const int t4   = lane & 3;      // 0..3

    float acc[4][4][4];
    #pragma unroll
    for (int i = 0; i < 4; i++)
        #pragma unroll
        for (int j = 0; j < 4; j++)
            #pragma unroll
            for (int k = 0; k < 4; k++) acc[i][j][k] = 0.f;

    // ---- A global-load setup: thread loads row m0+(tid>>1), 8 cols ----
    const int am   = m0 + (tid >> 1);
    const bool amOK = am < M;
    long long arow = (alen > 0)
        ? (long long)(am / alen) * L_ + astart + (am % alen)
        : (long long)am;
    const float* Aptr = A + arow * (long long)lda + (tid & 1) * 8;
    const int a_sm = tid >> 1;
    const int a_sk = (tid & 1) * 8;

    // ---- B global-load setup ----
    const float* Bptr;
    bool bOK;
    int b_sk, b_sn;
    if (!TRANSB) {
        int kr = tid >> 4;            // 0..15
        int cn = (tid & 15) * 8;      // 0..120
        bOK  = (n0 + cn) < N;
        Bptr = B + (long long)kr * ldb + n0 + cn;
        b_sk = kr; b_sn = cn;
    } else {
        int bn = tid >> 1;            // 0..127
        int ck = (tid & 1) * 8;
        bOK  = (n0 + bn) < N;
        Bptr = B + (long long)(n0 + bn) * ldb + ck;
        b_sk = ck; b_sn = bn;
    }

    float4 ra0, ra1, rb0, rb1;
    const float4 z4 = make_float4(0.f, 0.f, 0.f, 0.f);

    auto ldg = [&](int k0) {
        if (amOK) {
            ra0 = *(const float4*)(Aptr + k0);
            ra1 = *(const float4*)(Aptr + k0 + 4);
        } else { ra0 = z4; ra1 = z4; }
        if (!TRANSB) {
            const float* p = Bptr + (long long)k0 * ldb;
            if (bOK) { rb0 = *(const float4*)p; rb1 = *(const float4*)(p + 4); }
            else     { rb0 = z4; rb1 = z4; }
        } else {
            if (bOK) { rb0 = *(const float4*)(Bptr + k0); rb1 = *(const float4*)(Bptr + k0 + 4); }
            else     { rb0 = z4; rb1 = z4; }
        }
    };

    auto sts = [&](int buf) {
        As[buf][a_sk + 0][a_sm] = f2tf32(ra0.x);
        As[buf][a_sk + 1][a_sm] = f2tf32(ra0.y);
        As[buf][a_sk + 2][a_sm] = f2tf32(ra0.z);
        As[buf][a_sk + 3][a_sm] = f2tf32(ra0.w);
        As[buf][a_sk + 4][a_sm] = f2tf32(ra1.x);
        As[buf][a_sk + 5][a_sm] = f2tf32(ra1.y);
        As[buf][a_sk + 6][a_sm] = f2tf32(ra1.z);
        As[buf][a_sk + 7][a_sm] = f2tf32(ra1.w);
        if (!TRANSB) {
            float4 c0 = make_float4(f2tf32(rb0.x), f2tf32(rb0.y), f2tf32(rb0.z), f2tf32(rb0.w));
            float4 c1 = make_float4(f2tf32(rb1.x), f2tf32(rb1.y), f2tf32(rb1.z), f2tf32(rb1.w));
            *(float4*)&Bs[buf][b_sk][b_sn]     = c0;
            *(float4*)&Bs[buf][b_sk][b_sn + 4] = c1;
        } else {
            Bs[buf][b_sk + 0][b_sn] = f2tf32(rb0.x);
            Bs[buf][b_sk + 1][b_sn] = f2tf32(rb0.y);
            Bs[buf][b_sk + 2][b_sn] = f2tf32(rb0.z);
            Bs[buf][b_sk + 3][b_sn] = f2tf32(rb0.w);
            Bs[buf][b_sk + 4][b_sn] = f2tf32(rb1.x);
            Bs[buf][b_sk + 5][b_sn] = f2tf32(rb1.y);
            Bs[buf][b_sk + 6][b_sn] = f2tf32(rb1.z);
            Bs[buf][b_sk + 7][b_sn] = f2tf32(rb1.w);
        }
    };

    auto compute = [&](int buf) {
        #pragma unroll
        for (int kb = 0; kb < 16; kb += 8) {
            uint32_t af[4][4], bf[4][2];
            #pragma unroll
            for (int mi = 0; mi < 4; mi++) {
                int mb = wm + mi * 16;
                af[mi][0] = __float_as_uint(As[buf][kb + t4    ][mb + g    ]);
                af[mi][1] = __float_as_uint(As[buf][kb + t4    ][mb + g + 8]);
                af[mi][2] = __float_as_uint(As[buf][kb + t4 + 4][mb + g    ]);
                af[mi][3] = __float_as_uint(As[buf][kb + t4 + 4][mb + g + 8]);
            }
            #pragma unroll
            for (int ni = 0; ni < 4; ni++) {
                int nb = wn + ni * 8;
                bf[ni][0] = __float_as_uint(Bs[buf][kb + t4    ][nb + g]);
                bf[ni][1] = __float_as_uint(Bs[buf][kb + t4 + 4][nb + g]);
            }
            #pragma unroll
            for (int mi = 0; mi < 4; mi++)
                #pragma unroll
                for (int ni = 0; ni < 4; ni++) {
                    asm volatile(
                        "mma.sync.aligned.m16n8k8.row.col.f32.tf32.tf32.f32 "
                        "{%0,%1,%2,%3},{%4,%5,%6,%7},{%8,%9},{%0,%1,%2,%3};"
                        : "+f"(acc[mi][ni][0]), "+f"(acc[mi][ni][1]),
                          "+f"(acc[mi][ni][2]), "+f"(acc[mi][ni][3])
                        : "r"(af[mi][0]), "r"(af[mi][1]),
                          "r"(af[mi][2]), "r"(af[mi][3]),
                          "r"(bf[ni][0]), "r"(bf[ni][1]));
                }
        }
    };

    // ---- pipelined main loop ----
    ldg(0);
    sts(0);
    __syncthreads();
    int cur = 0;
    for (int k0 = 16;; k0 += 16) {
        bool more = k0 < K;
        if (more) ldg(k0);
        compute(cur);
        if (!more) break;
        sts(cur ^ 1);
        __syncthreads();
        cur ^= 1;
    }

    // ---- epilogue ----
    float gate = 1.0f;
    if (gate_logit) gate = 1.0f / (1.0f + expf(-(*gate_logit)));

    #pragma unroll
    for (int mi = 0; mi < 4; mi++) {
        #pragma unroll
        for (int rr = 0; rr < 2; rr++) {
            int m = m0 + wm + mi * 16 + g + rr * 8;
            if (m >= M) continue;
            long long crow = (clen > 0)
                ? (long long)(m / clen) * L_ + cstart + (m % clen)
                : (long long)m;
            float* cp = C + crow * (long long)ldc;
            #pragma unroll
            for (int ni = 0; ni < 4; ni++) {
                int n = n0 + wn + ni * 8 + t4 * 2;
                if (n >= N) continue;
                float v0 = acc[mi][ni][rr * 2 + 0];
                float v1 = acc[mi][ni][rr * 2 + 1];
                if (bias) { v0 += bias[n]; v1 += bias[n + 1]; }
                cp[n]     = v0 * gate;
                cp[n + 1] = v1 * gate;
            }
        }
    }
}

// ---------------------------------------------------------------------------
// Row softmax over segment-packed g_S; scale = (1/32)/clip(exp(log_temp))
// ---------------------------------------------------------------------------
__global__ void softmax_kernel(const float* __restrict__ log_temp)
{
    int row = blockIdx.x;           // b*L + l
    int b = row / L_;
    int l = row - b * L_;

    int seg = 0;
    #pragma unroll
    for (int s2 = 1; s2 < NSEG; s2++)
        if (l >= c_start[s2]) seg = s2;

    const int n   = 128 * (seg + 1);
    const int len = c_len[seg];
    float* p = g_S + c_base[seg] + ((long long)b * len + (l - c_start[seg])) * (long long)n;

    float t = expf(*log_temp);
    t = fminf(fmaxf(t, 0.05f), 1.0f);
    const float scale = (1.0f / 32.0f) / t;

    __shared__ float sh[8];
    const int lane = threadIdx.x & 31;
    const int w    = threadIdx.x >> 5;

    float m = -1e30f;
    for (int j = threadIdx.x; j < n; j += 256) m = fmaxf(m, p[j] * scale);
    #pragma unroll
    for (int o = 16; o; o >>= 1) m = fmaxf(m, __shfl_xor_sync(0xffffffffu, m, o));
    if (lane == 0) sh[w] = m;
    __syncthreads();
    m = sh[lane & 7];
    #pragma unroll
    for (int o = 4; o; o >>= 1) m = fmaxf(m, __shfl_xor_sync(0xffffffffu, m, o));

    float sum = 0.f;
    for (int j = threadIdx.x; j < n; j += 256) {
        float e = expf(p[j] * scale - m);
        p[j] = e;
        sum += e;
    }
    #pragma unroll
    for (int o = 16; o; o >>= 1) sum += __shfl_xor_sync(0xffffffffu, sum, o);
    __syncthreads();
    if (lane == 0) sh[w] = sum;
    __syncthreads();
    sum = sh[lane & 7];
    #pragma unroll
    for (int o = 4; o; o >>= 1) sum += __shfl_xor_sync(0xffffffffu, sum, o);

    const float inv = 1.0f / sum;
    for (int j = threadIdx.x; j < n; j += 256) p[j] *= inv;
}

// Pack wk1|wv1 -> g_w12 [1024x128], bk1|bv1 -> g_b12 [128]
__global__ void pack_w12_kernel(const float* __restrict__ wk1,
                                const float* __restrict__ wv1,
                                const float* __restrict__ bk1,
                                const float* __restrict__ bv1)
{
    int idx = blockIdx.x * 256 + threadIdx.x;
    if (idx < 1024 * 64) {
        int k = idx >> 6, j = idx & 63;
        g_w12[k * 128 + j]      = wk1[idx];
        g_w12[k * 128 + 64 + j] = wv1[idx];
    }
    if (idx < 64) {
        g_b12[idx]      = bk1[idx];
        g_b12[64 + idx] = bv1[idx];
    }
}

__global__ void tail_kernel(float* out, long long off)
{
    if (threadIdx.x < 2) out[off + threadIdx.x] = 0.f;
}

// ---------------------------------------------------------------------------
static void launch_tgemm(bool transB,
                         const float* A, int lda,
                         const float* B, int ldb,
                         float* C, int ldc,
                         int M, int N, int K,
                         int alen, int astart, int clen, int cstart,
                         const float* bias, const float* gate)
{
    dim3 grid((N + 127) / 128, (M + 127) / 128);
    if (transB)
        tgemm<1><<<grid, 256>>>(A, lda, B, ldb, C, ldc, M, N, K,
                                alen, astart, clen, cstart, bias, gate);
    else
        tgemm<0><<<grid, 256>>>(A, lda, B, ldb, C, ldc, M, N, K,
                                alen, astart, clen, cstart, bias, gate);
}

extern "C" void kernel_launch(void* const* d_in, const int* in_sizes, int n_in,
                              void* d_out, int out_size)
{
    const float* x   = (const float*)d_in[0];
    const float* mem = (const float*)d_in[1];
    const float* Wq  = (const float*)d_in[2];
    const float* Wk  = (const float*)d_in[3];
    const float* Wv  = (const float*)d_in[4];
    const float* wk1 = (const float*)d_in[5];
    const float* bk1 = (const float*)d_in[6];
    const float* wk2 = (const float*)d_in[7];
    const float* bk2 = (const float*)d_in[8];
    const float* wv1 = (const float*)d_in[9];
    const float* bv1 = (const float*)d_in[10];
    const float* wv2 = (const float*)d_in[11];
    const float* bv2 = (const float*)d_in[12];
    const float* gk  = (const float*)d_in[13];
    const float* gv  = (const float*)d_in[14];
    const float* lt  = (const float*)d_in[15];
    float* out = (float*)d_out;

    float *Q, *Kp, *Vp, *S, *MC, *mid, *w12, *b12;
    cudaGetSymbolAddress((void**)&Q,   g_Q);
    cudaGetSymbolAddress((void**)&Kp,  g_K);
    cudaGetSymbolAddress((void**)&Vp,  g_V);
    cudaGetSymbolAddress((void**)&S,   g_S);
    cudaGetSymbolAddress((void**)&MC,  g_MC);
    cudaGetSymbolAddress((void**)&mid, g_mid);
    cudaGetSymbolAddress((void**)&w12, g_w12);
    cudaGetSymbolAddress((void**)&b12, g_b12);

    // 0) pack bottleneck down-proj weights (independent of GEMMs before it)
    pack_w12_kernel<<<256, 256>>>(wk1, wv1, bk1, bv1);

    // 1) projections
    launch_tgemm(false, x,   C_, Wq, C_, Q,  C_, B_ * L_,    C_, C_, 0,0,0,0, nullptr, nullptr);
    launch_tgemm(false, mem, C_, Wk, C_, Kp, C_, NSEG * 128, C_, C_, 0,0,0,0, nullptr, nullptr);
    launch_tgemm(false, mem, C_, Wv, C_, Vp, C_, NSEG * 128, C_, C_, 0,0,0,0, nullptr, nullptr);

    // 2) scores per segment (flattened M = 64*len, A rows remapped into Q)
    for (int i = 0; i < NSEG; i++) {
        int n = 128 * (i + 1), len = h_len[i], s = h_start[i];
        launch_tgemm(true,
                     Q, C_, Kp, C_, S + h_base[i], n,
                     B_ * len, n, C_,
                     len, s, 0, 0, nullptr, nullptr);
    }

    // 3) softmax in-place
    softmax_kernel<<<B_ * L_, 256>>>(lt);

    // 4) attn @ V per segment (C rows remapped into MC)
    for (int i = 0; i < NSEG; i++) {
        int n = 128 * (i + 1), len = h_len[i], s = h_start[i];
        launch_tgemm(false,
                     S + h_base[i], n, Vp, C_, MC, C_,
                     B_ * len, C_, n,
                     0, 0, len, s, nullptr, nullptr);
    }

    // 5) fused mid GEMM: mid = MC @ [wk1|wv1] + [bk1|bv1]   (43520 x 128)
    launch_tgemm(false, MC, C_, w12, 128, mid, 128, B_ * L_, 128, C_, 0,0,0,0, b12, nullptr);

    // 6) up-projections with gate epilogue
    launch_tgemm(false, mid,      128, wk2, C_, out, C_,
                 B_ * L_, C_, 64, 0,0,0,0, bk2, gk);
    launch_tgemm(false, mid + 64, 128, wv2, C_, out + (long long)B_ * L_ * C_, C_,
                 B_ * L_, C_, 64, 0,0,0,0, bv2, gv);

    // 7) trailing two scalar zeros
    tail_kernel<<<1, 32>>>(out, 2LL * B_ * L_ * C_);
}